// round 1
// baseline (speedup 1.0000x reference)
#include <cuda_runtime.h>
#include <cuda_bf16.h>
#include <cstdint>

// The reference pipeline is mathematically the identity:
//   recomb = [mag*cos(ph), mag*sin(ph)] == [re, im] exactly;
//   INV_BASIS is built from pinv(scale*FB) which is a LEFT inverse of the
//   full-column-rank forward basis, so per-frame y_t = (1/scale)*w^2 .* x_t;
//   overlap-add gives (1/scale)*ws[n]*x_pad[n]; dividing by ws and scaling
//   by scale yields x_pad; the final crop [pad:-pad] returns the input.
// Output (32,1,160000) == input (32,160000) reshaped. => pure D2D copy.

__global__ void stft_identity_copy(const float4* __restrict__ in,
                                   float4* __restrict__ out,
                                   int n4) {
    int i = blockIdx.x * blockDim.x + threadIdx.x;
    int stride = gridDim.x * blockDim.x;
    for (; i < n4; i += stride) {
        out[i] = in[i];
    }
}

__global__ void stft_identity_copy_tail(const float* __restrict__ in,
                                        float* __restrict__ out,
                                        int start, int n) {
    int i = start + blockIdx.x * blockDim.x + threadIdx.x;
    if (i < n) out[i] = in[i];
}

extern "C" void kernel_launch(void* const* d_in, const int* in_sizes, int n_in,
                              void* d_out, int out_size) {
    const float* in = (const float*)d_in[0];
    float* out = (float*)d_out;

    int n = out_size;            // 32*160000 = 5,120,000 floats
    int n4 = n >> 2;             // 1,280,000 float4
    int tail_start = n4 << 2;

    if (n4 > 0) {
        int threads = 256;
        int blocks = (n4 + threads - 1) / threads;   // ~5000 blocks, ~34 waves
        stft_identity_copy<<<blocks, threads>>>(
            (const float4*)in, (float4*)out, n4);
    }
    if (tail_start < n) {
        int rem = n - tail_start;
        stft_identity_copy_tail<<<(rem + 255) / 256, 256>>>(in, out, tail_start, n);
    }
}